// round 11
// baseline (speedup 1.0000x reference)
#include <cuda_runtime.h>
#include <cuda_fp16.h>
#include <cstdint>

#define BATCH 16
#define NQ    16384
#define CH    64
#define NKV   256
#define EPS   1e-5f
#define LOG2E 1.44269504088896340736f

// Scratch (device globals — no allocation allowed)
__device__ float  g_xconv[BATCH * NKV * CH];  // conv output [b*256+pos][c]
__device__ __half g_Gh[BATCH * 16384];        // G frags (pre-scaled 0.125*log2e)
__device__ __half g_VWh[BATCH * 16384];       // VW frags
__device__ float  g_sbias[BATCH * NKV];       // log2e*0.125*(bq . k_j)

__device__ __forceinline__ uint32_t to_tf32(float f) {
    uint32_t r; asm("cvt.rna.tf32.f32 %0, %1;" : "=r"(r) : "f"(f)); return r;
}
__device__ __forceinline__ uint32_t pack_h2(float lo, float hi) {
    __half2 h = __floats2half2_rn(lo, hi);
    return *(uint32_t*)&h;
}

// tf32: D += A(16x8) @ B(8x8)
__device__ __forceinline__ void mma_tf32(float* d, const uint32_t* a,
                                         uint32_t b0, uint32_t b1) {
    asm volatile(
        "mma.sync.aligned.m16n8k8.row.col.f32.tf32.tf32.f32 "
        "{%0,%1,%2,%3}, {%4,%5,%6,%7}, {%8,%9}, {%0,%1,%2,%3};"
        : "+f"(d[0]), "+f"(d[1]), "+f"(d[2]), "+f"(d[3])
        : "r"(a[0]), "r"(a[1]), "r"(a[2]), "r"(a[3]), "r"(b0), "r"(b1));
}
// fp16: D += A(16x16) @ B(16x8), fp32 accum
__device__ __forceinline__ void mma_f16(float* d, const uint32_t* a,
                                        uint32_t b0, uint32_t b1) {
    asm volatile(
        "mma.sync.aligned.m16n8k16.row.col.f32.f16.f16.f32 "
        "{%0,%1,%2,%3}, {%4,%5,%6,%7}, {%8,%9}, {%0,%1,%2,%3};"
        : "+f"(d[0]), "+f"(d[1]), "+f"(d[2]), "+f"(d[3])
        : "r"(a[0]), "r"(a[1]), "r"(a[2]), "r"(a[3]), "r"(b0), "r"(b1));
}

// ---------------------------------------------------------------------------
// Kernel A: strided conv as GEMM via tf32 mma.sync, DOUBLE-BUFFERED smem.
// One __syncthreads per K-iteration; LDG of iter k+1 overlaps compute of k.
// ---------------------------------------------------------------------------
__global__ void __launch_bounds__(256, 1) conv_kernel(
    const float* __restrict__ inp,
    const float* __restrict__ convw,
    const float* __restrict__ convb)
{
    __shared__ float sA[2][32 * 68];
    __shared__ float sW[2][64 * 72];

    int t = threadIdx.x, lane = t & 31, w = t >> 5;
    int lq = lane >> 2, lr = lane & 3;
    int rg16 = (w >> 2) * 16;
    int cb   = (w & 3) * 16;

    int rarr[2], kkarr[2], rowbase[2];
#pragma unroll
    for (int it = 0; it < 2; ++it) {
        int f4i = it * 256 + t;
        int r   = f4i >> 4;
        int kk  = (f4i & 15) * 4;
        int rg  = blockIdx.x * 32 + r;
        int b   = rg >> 8;
        int patch = rg & 255;
        int pi  = patch >> 4, pj = patch & 15;
        rarr[it]  = r;
        kkarr[it] = kk;
        rowbase[it] = (b << 14) + (pi << 10) + (pj << 3);
    }
    int kinarr[4], c4arr[4];
#pragma unroll
    for (int it = 0; it < 4; ++it) {
        int f4i = it * 256 + t;
        kinarr[it] = f4i >> 4;
        c4arr[it]  = (f4i & 15) * 4;
    }

    float acc[2][4] = {};
    float4 pa[2], pw[4];

    // prefetch iter 0 and commit to buf 0
    {
#pragma unroll
        for (int it = 0; it < 2; ++it)
            pa[it] = *(const float4*)&inp[(rowbase[it] << 6) + kkarr[it]];
#pragma unroll
        for (int it = 0; it < 4; ++it)
            pw[it] = *(const float4*)&convw[kinarr[it] * 64 + c4arr[it]];
#pragma unroll
        for (int it = 0; it < 2; ++it) {
            float4 v = pa[it];
            uint4 u = make_uint4(to_tf32(v.x), to_tf32(v.y), to_tf32(v.z), to_tf32(v.w));
            *(uint4*)&sA[0][rarr[it] * 68 + kkarr[it]] = u;
        }
#pragma unroll
        for (int it = 0; it < 4; ++it) {
            float4 v = pw[it];
            uint4 u = make_uint4(to_tf32(v.x), to_tf32(v.y), to_tf32(v.z), to_tf32(v.w));
            *(uint4*)&sW[0][kinarr[it] * 72 + c4arr[it]] = u;
        }
    }
    __syncthreads();

    for (int kc = 0; kc < 64; ++kc) {
        int cur = kc & 1;
        // issue prefetch of next iter early (latency overlaps compute below)
        if (kc + 1 < 64) {
            int kn = kc + 1, di = kn >> 3, dj = kn & 7;
#pragma unroll
            for (int it = 0; it < 2; ++it)
                pa[it] = *(const float4*)&inp[((rowbase[it] + di * 128 + dj) << 6) + kkarr[it]];
#pragma unroll
            for (int it = 0; it < 4; ++it)
                pw[it] = *(const float4*)&convw[(kn << 12) + kinarr[it] * 64 + c4arr[it]];
        }

        // compute from current buffer
#pragma unroll
        for (int k = 0; k < 8; ++k) {
            uint32_t a[4];
            a[0] = __float_as_uint(sA[cur][(rg16 + lq) * 68 + k * 8 + lr]);
            a[1] = __float_as_uint(sA[cur][(rg16 + 8 + lq) * 68 + k * 8 + lr]);
            a[2] = __float_as_uint(sA[cur][(rg16 + lq) * 68 + k * 8 + lr + 4]);
            a[3] = __float_as_uint(sA[cur][(rg16 + 8 + lq) * 68 + k * 8 + lr + 4]);
#pragma unroll
            for (int nb = 0; nb < 2; ++nb) {
                uint32_t b0 = __float_as_uint(sW[cur][(k * 8 + lr) * 72 + cb + nb * 8 + lq]);
                uint32_t b1 = __float_as_uint(sW[cur][(k * 8 + lr + 4) * 72 + cb + nb * 8 + lq]);
                mma_tf32(acc[nb], a, b0, b1);
            }
        }

        // commit next tile into the other buffer
        if (kc + 1 < 64) {
            int nxt = cur ^ 1;
#pragma unroll
            for (int it = 0; it < 2; ++it) {
                float4 v = pa[it];
                uint4 u = make_uint4(to_tf32(v.x), to_tf32(v.y), to_tf32(v.z), to_tf32(v.w));
                *(uint4*)&sA[nxt][rarr[it] * 68 + kkarr[it]] = u;
            }
#pragma unroll
            for (int it = 0; it < 4; ++it) {
                float4 v = pw[it];
                uint4 u = make_uint4(to_tf32(v.x), to_tf32(v.y), to_tf32(v.z), to_tf32(v.w));
                *(uint4*)&sW[nxt][kinarr[it] * 72 + c4arr[it]] = u;
            }
        }
        __syncthreads();
    }

    int row0 = blockIdx.x * 32 + rg16 + lq;
#pragma unroll
    for (int nb = 0; nb < 2; ++nb) {
        int c = cb + nb * 8 + 2 * lr;
        float cb0 = convb[c], cb1 = convb[c + 1];
        *(float2*)&g_xconv[row0 * 64 + c] =
            make_float2(acc[nb][0] + cb0, acc[nb][1] + cb1);
        *(float2*)&g_xconv[(row0 + 8) * 64 + c] =
            make_float2(acc[nb][2] + cb0, acc[nb][3] + cb1);
    }
}

// ---------------------------------------------------------------------------
// Kernel B: per kv position — LN, kv proj; emits FRAGMENT-ORDERED fp16 G/VW.
// G pre-scaled by 0.125*log2(e); sbias by 0.125*log2(e)  (softmax uses exp2).
// ---------------------------------------------------------------------------
__global__ void __launch_bounds__(256, 1) kv_kernel(
    const float* __restrict__ Wq,  const float* __restrict__ bq,
    const float* __restrict__ Wkv, const float* __restrict__ bkv,
    const float* __restrict__ Wo,
    const float* __restrict__ gamma, const float* __restrict__ beta)
{
    extern __shared__ float sm[];
    float* sWkv = sm;            // 8192
    float* sWo  = sm + 8192;     // 4096
    float* sWqT = sm + 12288;    // 64*65
    float* sx   = sm + 16448;
    float* sxn  = sm + 16512;
    float* skv  = sm + 16576;
    float* sgam = sm + 16704;
    float* sbet = sm + 16768;
    float* sbq  = sm + 16832;
    float* sbkv = sm + 16896;
    float* sstat= sm + 17024;

    int t = threadIdx.x;

#pragma unroll
    for (int it = 0; it < 8; ++it)
        ((float4*)sWkv)[it * 256 + t] = ((const float4*)Wkv)[it * 256 + t];
#pragma unroll
    for (int it = 0; it < 4; ++it)
        ((float4*)sWo)[it * 256 + t] = ((const float4*)Wo)[it * 256 + t];
#pragma unroll
    for (int it = 0; it < 4; ++it) {
        int f4i = it * 256 + t;
        int d = f4i >> 4, cc = (f4i & 15) * 4;
        float4 v = ((const float4*)Wq)[f4i];
        sWqT[(cc + 0) * 65 + d] = v.x;
        sWqT[(cc + 1) * 65 + d] = v.y;
        sWqT[(cc + 2) * 65 + d] = v.z;
        sWqT[(cc + 3) * 65 + d] = v.w;
    }
    if (t < 64)  { sgam[t] = gamma[t]; sbet[t] = beta[t]; sbq[t] = bq[t]; }
    if (t < 128) { sbkv[t] = bkv[t]; }
    __syncthreads();

    for (int p = 0; p < 8; ++p) {
        int j = blockIdx.x * 8 + p;
        if (t < 64) sx[t] = g_xconv[j * 64 + t];
        __syncthreads();

        if (t < 32) {
            float a = sx[t], b2 = sx[t + 32];
            float s = a + b2;
            float q = a * a + b2 * b2;
#pragma unroll
            for (int off = 16; off > 0; off >>= 1) {
                s += __shfl_xor_sync(0xffffffffu, s, off);
                q += __shfl_xor_sync(0xffffffffu, q, off);
            }
            if (t == 0) {
                float mean = s * (1.0f / 64.0f);
                sstat[0] = mean;
                sstat[1] = rsqrtf(q * (1.0f / 64.0f) - mean * mean + EPS);
            }
        }
        __syncthreads();
        if (t < 64)
            sxn[t] = (sx[t] - sstat[0]) * sstat[1] * sgam[t] + sbet[t];
        __syncthreads();

        if (t < 128) {
            float a = sbkv[t];
#pragma unroll 16
            for (int c = 0; c < 64; ++c)
                a += sxn[c] * sWkv[c * 128 + t];
            skv[t] = a;
        }
        __syncthreads();

        int b = j >> 8, pos = j & 255;
        if (t < 64) {
            float a = 0.0f;
#pragma unroll 16
            for (int c = 0; c < 64; ++c)
                a += sWqT[c * 65 + t] * skv[c];
            int nt = pos >> 3, lqj = pos & 7;
            int d = t, ks = d >> 4, dd = d & 15;
            int wrd = dd >> 3, lr = (dd >> 1) & 3, h = dd & 1;
            int idx = ((((b * 32 + nt) * 4 + ks) * 32 + lqj * 4 + lr) * 2 + wrd) * 2 + h;
            g_Gh[idx] = __float2half_rn(0.125f * LOG2E * a);
        } else if (t < 128) {
            int cc = t - 64;
            float a = 0.0f;
#pragma unroll 16
            for (int d = 0; d < 64; ++d)
                a += skv[64 + d] * sWo[d * 64 + cc];
            int ct = cc >> 3, lqc = cc & 7;
            int ks = pos >> 4, jj = pos & 15;
            int wrd = jj >> 3, lr = (jj >> 1) & 3, h = jj & 1;
            int idx = ((((b * 8 + ct) * 16 + ks) * 32 + lqc * 4 + lr) * 2 + wrd) * 2 + h;
            g_VWh[idx] = __float2half_rn(a);
        } else if (t == 128) {
            float a = 0.0f;
            for (int c = 0; c < 64; ++c)
                a += sbq[c] * skv[c];
            g_sbias[(b << 8) + pos] = 0.125f * LOG2E * a;
        }
        __syncthreads();
    }
}

// ---------------------------------------------------------------------------
// Kernel C: fp16 attention, j-SPLIT across warp pairs for 2x occupancy.
// 512 threads: warp w -> (r = w>>1 : 16-row group, h = w&1 : 128-col j-half).
// GEMM1: 16 nt x 4 ks = 64 mma; softmax with cross-pair max/sum via smem;
// GEMM2: k-split (8 ks per warp), partial O combined via smem (aliases sG).
// smem: sG|sO 32KB, sVW 32KB, sbias 1KB, smx 1KB, ssum 1KB, sbo 256B
// ---------------------------------------------------------------------------
#define AT_SMEM 68864

__global__ void __launch_bounds__(512, 1) attn_kernel(
    const float* __restrict__ inp,
    const float* __restrict__ bo_g,
    float* __restrict__ out)
{
    extern __shared__ char smem[];
    uint2* sG    = (uint2*)smem;                    // 32KB frag blob (GEMM1)
    float* sO    = (float*)smem;                    // 32KB partial O (aliases sG)
    uint2* sVW   = (uint2*)(smem + 32768);          // 32KB
    float* sbias = (float*)(smem + 65536);          // 256 f
    float* smx   = (float*)(smem + 66560);          // 2 x 128 f
    float* ssum  = (float*)(smem + 67584);          // 2 x 128 f
    float* sbo   = (float*)(smem + 68608);          // 64 f

    int t = threadIdx.x, lane = t & 31, w = t >> 5;
    int lq = lane >> 2, lr = lane & 3;
    int h = w & 1, r = w >> 1;
    int m0 = r * 16;
    int b  = blockIdx.y;
    int n0 = blockIdx.x * 128;

    // ---- A-fragments of X from global, fp16 ----
    uint32_t afr[4][4];
    {
        const float* x0 = inp + ((size_t)(b * NQ + n0 + m0 + lq)) * 64;
        const float* x1 = x0 + 8 * 64;
#pragma unroll
        for (int ks = 0; ks < 4; ++ks) {
            float2 u0 = *(const float2*)&x0[ks * 16 + 2 * lr];
            float2 u1 = *(const float2*)&x1[ks * 16 + 2 * lr];
            float2 u2 = *(const float2*)&x0[ks * 16 + 8 + 2 * lr];
            float2 u3 = *(const float2*)&x1[ks * 16 + 8 + 2 * lr];
            afr[ks][0] = pack_h2(u0.x, u0.y);
            afr[ks][1] = pack_h2(u1.x, u1.y);
            afr[ks][2] = pack_h2(u2.x, u2.y);
            afr[ks][3] = pack_h2(u3.x, u3.y);
        }
    }

    // ---- stage fragment blobs ----
    {
        const uint4* gG = (const uint4*)g_Gh + b * 2048;
        const uint4* gV = (const uint4*)g_VWh + b * 2048;
#pragma unroll
        for (int it = 0; it < 4; ++it) {
            ((uint4*)sG)[it * 512 + t]  = gG[it * 512 + t];
            ((uint4*)sVW)[it * 512 + t] = gV[it * 512 + t];
        }
    }
    if (t < 64) ((float4*)sbias)[t] = ((const float4*)(g_sbias + (b << 8)))[t];
    if (t < 16) ((float4*)sbo)[t]   = ((const float4*)bo_g)[t];
    __syncthreads();

    // ---- GEMM1: S(16 rows x 128 cols of this half) ----
    float acc[16][4];
#pragma unroll
    for (int nt = 0; nt < 16; ++nt)
#pragma unroll
        for (int i = 0; i < 4; ++i) acc[nt][i] = 0.0f;

#pragma unroll
    for (int ks = 0; ks < 4; ++ks) {
#pragma unroll
        for (int nt = 0; nt < 16; ++nt) {
            uint2 bb = sG[((h * 16 + nt) * 4 + ks) * 32 + lane];
            mma_f16(acc[nt], afr[ks], bb.x, bb.y);
        }
    }

    // ---- local bias + max (quad reduce) ----
    float mx0 = -1e30f, mx1 = -1e30f;
#pragma unroll
    for (int nt = 0; nt < 16; ++nt) {
        int c = (h * 16 + nt) * 8 + 2 * lr;
        float bi0 = sbias[c], bi1 = sbias[c + 1];
        acc[nt][0] += bi0; acc[nt][1] += bi1;
        acc[nt][2] += bi0; acc[nt][3] += bi1;
        mx0 = fmaxf(mx0, fmaxf(acc[nt][0], acc[nt][1]));
        mx1 = fmaxf(mx1, fmaxf(acc[nt][2], acc[nt][3]));
    }
    mx0 = fmaxf(mx0, __shfl_xor_sync(0xffffffffu, mx0, 1));
    mx0 = fmaxf(mx0, __shfl_xor_sync(0xffffffffu, mx0, 2));
    mx1 = fmaxf(mx1, __shfl_xor_sync(0xffffffffu, mx1, 1));
    mx1 = fmaxf(mx1, __shfl_xor_sync(0xffffffffu, mx1, 2));
    if (lr == 0) {
        smx[h * 128 + m0 + lq]     = mx0;
        smx[h * 128 + m0 + 8 + lq] = mx1;
    }
    __syncthreads();

    // ---- combined max, exp2, pack, local sums ----
    float M0 = fmaxf(smx[m0 + lq],     smx[128 + m0 + lq]);
    float M1 = fmaxf(smx[m0 + 8 + lq], smx[128 + m0 + 8 + lq]);
    float sum0 = 0.0f, sum1 = 0.0f;
    uint32_t pacc[32];
#pragma unroll
    for (int nt = 0; nt < 16; ++nt) {
        float e0 = exp2f(acc[nt][0] - M0);
        float e1 = exp2f(acc[nt][1] - M0);
        float e2 = exp2f(acc[nt][2] - M1);
        float e3 = exp2f(acc[nt][3] - M1);
        sum0 += e0 + e1;
        sum1 += e2 + e3;
        pacc[2 * nt]     = pack_h2(e0, e1);
        pacc[2 * nt + 1] = pack_h2(e2, e3);
    }
    sum0 += __shfl_xor_sync(0xffffffffu, sum0, 1);
    sum0 += __shfl_xor_sync(0xffffffffu, sum0, 2);
    sum1 += __shfl_xor_sync(0xffffffffu, sum1, 1);
    sum1 += __shfl_xor_sync(0xffffffffu, sum1, 2);
    if (lr == 0) {
        ssum[h * 128 + m0 + lq]     = sum0;
        ssum[h * 128 + m0 + 8 + lq] = sum1;
    }
    __syncthreads();
    float rv0 = 1.0f / (ssum[m0 + lq]     + ssum[128 + m0 + lq]);
    float rv1 = 1.0f / (ssum[m0 + 8 + lq] + ssum[128 + m0 + 8 + lq]);

    // ---- GEMM2 partial: ks_g = h*8 + ks (this warp's j-half) ----
    float acc2[8][4];
#pragma unroll
    for (int ct = 0; ct < 8; ++ct)
#pragma unroll
        for (int i = 0; i < 4; ++i) acc2[ct][i] = 0.0f;

#pragma unroll
    for (int ks = 0; ks < 8; ++ks) {
        const uint32_t* pa = &pacc[4 * ks];
#pragma unroll
        for (int ct = 0; ct < 8; ++ct) {
            uint2 bb = sVW[(ct * 16 + h * 8 + ks) * 32 + lane];
            mma_f16(acc2[ct], pa, bb.x, bb.y);
        }
    }

    // ---- combine partner partials via sO (aliases dead sG) ----
    if (h == 1) {
#pragma unroll
        for (int ct = 0; ct < 8; ++ct) {
            int c = ct * 8 + 2 * lr;
            *(float2*)&sO[(m0 + lq) * 64 + c]     = make_float2(acc2[ct][0], acc2[ct][1]);
            *(float2*)&sO[(m0 + 8 + lq) * 64 + c] = make_float2(acc2[ct][2], acc2[ct][3]);
        }
    }
    __syncthreads();
    if (h == 0) {
        size_t rg = (size_t)(b * NQ + n0 + m0 + lq) * 64;
#pragma unroll
        for (int ct = 0; ct < 8; ++ct) {
            int c = ct * 8 + 2 * lr;
            float2 p0 = *(const float2*)&sO[(m0 + lq) * 64 + c];
            float2 p1 = *(const float2*)&sO[(m0 + 8 + lq) * 64 + c];
            float2 o0 = make_float2((acc2[ct][0] + p0.x) * rv0 + sbo[c],
                                    (acc2[ct][1] + p0.y) * rv0 + sbo[c + 1]);
            float2 o1 = make_float2((acc2[ct][2] + p1.x) * rv1 + sbo[c],
                                    (acc2[ct][3] + p1.y) * rv1 + sbo[c + 1]);
            *(float2*)&out[rg + c] = o0;
            *(float2*)&out[rg + 8 * 64 + c] = o1;
        }
    }
}

// ---------------------------------------------------------------------------
extern "C" void kernel_launch(void* const* d_in, const int* in_sizes, int n_in,
                              void* d_out, int out_size)
{
    const float* inp   = (const float*)d_in[0];
    const float* Wq    = (const float*)d_in[1];
    const float* bq    = (const float*)d_in[2];
    const float* Wkv   = (const float*)d_in[3];
    const float* bkv   = (const float*)d_in[4];
    const float* Wo    = (const float*)d_in[5];
    const float* bo    = (const float*)d_in[6];
    const float* convw = (const float*)d_in[7];
    const float* convb = (const float*)d_in[8];
    const float* gamma = (const float*)d_in[9];
    const float* beta  = (const float*)d_in[10];
    float* out = (float*)d_out;

    const int smemB = 17026 * 4;
    cudaFuncSetAttribute(kv_kernel,   cudaFuncAttributeMaxDynamicSharedMemorySize, smemB);
    cudaFuncSetAttribute(attn_kernel, cudaFuncAttributeMaxDynamicSharedMemorySize, AT_SMEM);

    conv_kernel<<<128, 256>>>(inp, convw, convb);
    kv_kernel<<<512, 256, smemB>>>(Wq, bq, Wkv, bkv, Wo, gamma, beta);
    attn_kernel<<<dim3(128, 16), 512, AT_SMEM>>>(inp, bo, out);
}

// round 13
// speedup vs baseline: 1.2166x; 1.2166x over previous
#include <cuda_runtime.h>
#include <cuda_fp16.h>
#include <cstdint>

#define BATCH 16
#define NQ    16384
#define CH    64
#define NKV   256
#define EPS   1e-5f
#define LOG2E 1.44269504088896340736f

// Scratch (device globals — no allocation allowed)
__device__ float  g_xconv[BATCH * NKV * CH];  // conv output [b*256+pos][c]
__device__ __half g_Gh[BATCH * 16384];        // G frags (pre-scaled 0.125*log2e)
__device__ __half g_VWh[BATCH * 16384];       // VW frags
__device__ float  g_sbias[BATCH * NKV];       // log2e*0.125*(bq . k_j)

__device__ __forceinline__ uint32_t smem_u32(const void* p) {
    uint32_t a;
    asm("{ .reg .u64 t; cvta.to.shared.u64 t, %1; cvt.u32.u64 %0, t; }" : "=r"(a) : "l"(p));
    return a;
}
__device__ __forceinline__ void cp_async16(uint32_t saddr, const void* gptr) {
    asm volatile("cp.async.cg.shared.global [%0], [%1], 16;" :: "r"(saddr), "l"(gptr));
}
__device__ __forceinline__ uint32_t to_tf32(float f) {
    uint32_t r; asm("cvt.rna.tf32.f32 %0, %1;" : "=r"(r) : "f"(f)); return r;
}
__device__ __forceinline__ uint32_t pack_h2(float lo, float hi) {
    __half2 h = __floats2half2_rn(lo, hi);
    return *(uint32_t*)&h;
}

// tf32: D += A(16x8) @ B(8x8)
__device__ __forceinline__ void mma_tf32(float* d, const uint32_t* a,
                                         uint32_t b0, uint32_t b1) {
    asm volatile(
        "mma.sync.aligned.m16n8k8.row.col.f32.tf32.tf32.f32 "
        "{%0,%1,%2,%3}, {%4,%5,%6,%7}, {%8,%9}, {%0,%1,%2,%3};"
        : "+f"(d[0]), "+f"(d[1]), "+f"(d[2]), "+f"(d[3])
        : "r"(a[0]), "r"(a[1]), "r"(a[2]), "r"(a[3]), "r"(b0), "r"(b1));
}
// fp16: D += A(16x16) @ B(16x8), fp32 accum
__device__ __forceinline__ void mma_f16(float* d, const uint32_t* a,
                                        uint32_t b0, uint32_t b1) {
    asm volatile(
        "mma.sync.aligned.m16n8k16.row.col.f32.f16.f16.f32 "
        "{%0,%1,%2,%3}, {%4,%5,%6,%7}, {%8,%9}, {%0,%1,%2,%3};"
        : "+f"(d[0]), "+f"(d[1]), "+f"(d[2]), "+f"(d[3])
        : "r"(a[0]), "r"(a[1]), "r"(a[2]), "r"(a[3]), "r"(b0), "r"(b1));
}

// ---------------------------------------------------------------------------
// Kernel A: strided conv as GEMM via tf32 mma.sync + 3-stage cp.async pipeline.
// One __syncthreads per K-iteration; stage kc+2 issued into buffer freed at
// kc-1. cp.async lands raw fp32; cvt.rna.tf32 applied at register load
// (restores RNA rounding — raw truncation failed accuracy in R12).
// Dynamic smem: 3 stages x (sA 32x68 + sW 64x72) = 81408 B.
// ---------------------------------------------------------------------------
#define CV_STAGE_F 6784            // floats per stage
#define CV_SMEM    (3 * CV_STAGE_F * 4)

__global__ void __launch_bounds__(256, 1) conv_kernel(
    const float* __restrict__ inp,
    const float* __restrict__ convw,
    const float* __restrict__ convb)
{
    extern __shared__ float cs[];
    float* sAb[3];
    float* sWb[3];
    uint32_t aA[3], aW[3];
#pragma unroll
    for (int s = 0; s < 3; ++s) {
        sAb[s] = cs + s * CV_STAGE_F;
        sWb[s] = cs + s * CV_STAGE_F + 2176;
        aA[s] = smem_u32(sAb[s]);
        aW[s] = smem_u32(sWb[s]);
    }

    int t = threadIdx.x, lane = t & 31, w = t >> 5;
    int lq = lane >> 2, lr = lane & 3;
    int rg16 = (w >> 2) * 16;
    int cb   = (w & 3) * 16;

    int rarr[2], kkarr[2], rowbase[2];
#pragma unroll
    for (int it = 0; it < 2; ++it) {
        int f4i = it * 256 + t;
        int r   = f4i >> 4;
        int kk  = (f4i & 15) * 4;
        int rg  = blockIdx.x * 32 + r;
        int b   = rg >> 8;
        int patch = rg & 255;
        int pi  = patch >> 4, pj = patch & 15;
        rarr[it]  = r;
        kkarr[it] = kk;
        rowbase[it] = (b << 14) + (pi << 10) + (pj << 3);
    }
    int kinarr[4], c4arr[4];
#pragma unroll
    for (int it = 0; it < 4; ++it) {
        int f4i = it * 256 + t;
        kinarr[it] = f4i >> 4;
        c4arr[it]  = (f4i & 15) * 4;
    }

    // per-thread smem byte offsets (stage-relative)
    uint32_t aoff[2], woff[4];
#pragma unroll
    for (int it = 0; it < 2; ++it) aoff[it] = (rarr[it] * 68 + kkarr[it]) * 4;
#pragma unroll
    for (int it = 0; it < 4; ++it) woff[it] = (kinarr[it] * 72 + c4arr[it]) * 4;

#define CV_STAGE(buf, kc) do {                                                 \
        int _di = (kc) >> 3, _dj = (kc) & 7;                                   \
        cp_async16(aA[buf] + aoff[0],                                          \
            &inp[((rowbase[0] + _di * 128 + _dj) << 6) + kkarr[0]]);           \
        cp_async16(aA[buf] + aoff[1],                                          \
            &inp[((rowbase[1] + _di * 128 + _dj) << 6) + kkarr[1]]);           \
        cp_async16(aW[buf] + woff[0], &convw[((kc) << 12) + kinarr[0] * 64 + c4arr[0]]); \
        cp_async16(aW[buf] + woff[1], &convw[((kc) << 12) + kinarr[1] * 64 + c4arr[1]]); \
        cp_async16(aW[buf] + woff[2], &convw[((kc) << 12) + kinarr[2] * 64 + c4arr[2]]); \
        cp_async16(aW[buf] + woff[3], &convw[((kc) << 12) + kinarr[3] * 64 + c4arr[3]]); \
        asm volatile("cp.async.commit_group;");                                \
    } while (0)

    float acc[2][4] = {};

    CV_STAGE(0, 0);
    CV_STAGE(1, 1);

    int cur = 0;
    for (int kc = 0; kc < 64; ++kc) {
        asm volatile("cp.async.wait_group 1;");
        __syncthreads();   // stage kc visible; compute of kc-1 finished by all

        if (kc + 2 < 64) {
            int nbuf = cur + 2; if (nbuf >= 3) nbuf -= 3;
            CV_STAGE(nbuf, kc + 2);
        }

        const float* A = sAb[cur];
        const float* W = sWb[cur];
#pragma unroll
        for (int k = 0; k < 8; ++k) {
            uint32_t a[4];
            a[0] = to_tf32(A[(rg16 + lq) * 68 + k * 8 + lr]);
            a[1] = to_tf32(A[(rg16 + 8 + lq) * 68 + k * 8 + lr]);
            a[2] = to_tf32(A[(rg16 + lq) * 68 + k * 8 + lr + 4]);
            a[3] = to_tf32(A[(rg16 + 8 + lq) * 68 + k * 8 + lr + 4]);
#pragma unroll
            for (int nb = 0; nb < 2; ++nb) {
                uint32_t b0 = to_tf32(W[(k * 8 + lr) * 72 + cb + nb * 8 + lq]);
                uint32_t b1 = to_tf32(W[(k * 8 + lr + 4) * 72 + cb + nb * 8 + lq]);
                mma_tf32(acc[nb], a, b0, b1);
            }
        }

        ++cur; if (cur == 3) cur = 0;
    }

    int row0 = blockIdx.x * 32 + rg16 + lq;
#pragma unroll
    for (int nb = 0; nb < 2; ++nb) {
        int c = cb + nb * 8 + 2 * lr;
        float cb0 = convb[c], cb1 = convb[c + 1];
        *(float2*)&g_xconv[row0 * 64 + c] =
            make_float2(acc[nb][0] + cb0, acc[nb][1] + cb1);
        *(float2*)&g_xconv[(row0 + 8) * 64 + c] =
            make_float2(acc[nb][2] + cb0, acc[nb][3] + cb1);
    }
#undef CV_STAGE
}

// ---------------------------------------------------------------------------
// Kernel B: per kv position — LN, kv proj; emits FRAGMENT-ORDERED fp16 G/VW.
// G pre-scaled by 0.125*log2(e); sbias by 0.125*log2(e)  (softmax uses exp2).
// ---------------------------------------------------------------------------
__global__ void __launch_bounds__(256, 1) kv_kernel(
    const float* __restrict__ Wq,  const float* __restrict__ bq,
    const float* __restrict__ Wkv, const float* __restrict__ bkv,
    const float* __restrict__ Wo,
    const float* __restrict__ gamma, const float* __restrict__ beta)
{
    extern __shared__ float sm[];
    float* sWkv = sm;            // 8192
    float* sWo  = sm + 8192;     // 4096
    float* sWqT = sm + 12288;    // 64*65
    float* sx   = sm + 16448;
    float* sxn  = sm + 16512;
    float* skv  = sm + 16576;
    float* sgam = sm + 16704;
    float* sbet = sm + 16768;
    float* sbq  = sm + 16832;
    float* sbkv = sm + 16896;
    float* sstat= sm + 17024;

    int t = threadIdx.x;

#pragma unroll
    for (int it = 0; it < 8; ++it)
        ((float4*)sWkv)[it * 256 + t] = ((const float4*)Wkv)[it * 256 + t];
#pragma unroll
    for (int it = 0; it < 4; ++it)
        ((float4*)sWo)[it * 256 + t] = ((const float4*)Wo)[it * 256 + t];
#pragma unroll
    for (int it = 0; it < 4; ++it) {
        int f4i = it * 256 + t;
        int d = f4i >> 4, cc = (f4i & 15) * 4;
        float4 v = ((const float4*)Wq)[f4i];
        sWqT[(cc + 0) * 65 + d] = v.x;
        sWqT[(cc + 1) * 65 + d] = v.y;
        sWqT[(cc + 2) * 65 + d] = v.z;
        sWqT[(cc + 3) * 65 + d] = v.w;
    }
    if (t < 64)  { sgam[t] = gamma[t]; sbet[t] = beta[t]; sbq[t] = bq[t]; }
    if (t < 128) { sbkv[t] = bkv[t]; }
    __syncthreads();

    for (int p = 0; p < 8; ++p) {
        int j = blockIdx.x * 8 + p;
        if (t < 64) sx[t] = g_xconv[j * 64 + t];
        __syncthreads();

        if (t < 32) {
            float a = sx[t], b2 = sx[t + 32];
            float s = a + b2;
            float q = a * a + b2 * b2;
#pragma unroll
            for (int off = 16; off > 0; off >>= 1) {
                s += __shfl_xor_sync(0xffffffffu, s, off);
                q += __shfl_xor_sync(0xffffffffu, q, off);
            }
            if (t == 0) {
                float mean = s * (1.0f / 64.0f);
                sstat[0] = mean;
                sstat[1] = rsqrtf(q * (1.0f / 64.0f) - mean * mean + EPS);
            }
        }
        __syncthreads();
        if (t < 64)
            sxn[t] = (sx[t] - sstat[0]) * sstat[1] * sgam[t] + sbet[t];
        __syncthreads();

        if (t < 128) {
            float a = sbkv[t];
#pragma unroll 16
            for (int c = 0; c < 64; ++c)
                a += sxn[c] * sWkv[c * 128 + t];
            skv[t] = a;
        }
        __syncthreads();

        int b = j >> 8, pos = j & 255;
        if (t < 64) {
            float a = 0.0f;
#pragma unroll 16
            for (int c = 0; c < 64; ++c)
                a += sWqT[c * 65 + t] * skv[c];
            int nt = pos >> 3, lqj = pos & 7;
            int d = t, ks = d >> 4, dd = d & 15;
            int wrd = dd >> 3, lr = (dd >> 1) & 3, h = dd & 1;
            int idx = ((((b * 32 + nt) * 4 + ks) * 32 + lqj * 4 + lr) * 2 + wrd) * 2 + h;
            g_Gh[idx] = __float2half_rn(0.125f * LOG2E * a);
        } else if (t < 128) {
            int cc = t - 64;
            float a = 0.0f;
#pragma unroll 16
            for (int d = 0; d < 64; ++d)
                a += skv[64 + d] * sWo[d * 64 + cc];
            int ct = cc >> 3, lqc = cc & 7;
            int ks = pos >> 4, jj = pos & 15;
            int wrd = jj >> 3, lr = (jj >> 1) & 3, h = jj & 1;
            int idx = ((((b * 8 + ct) * 16 + ks) * 32 + lqc * 4 + lr) * 2 + wrd) * 2 + h;
            g_VWh[idx] = __float2half_rn(a);
        } else if (t == 128) {
            float a = 0.0f;
            for (int c = 0; c < 64; ++c)
                a += sbq[c] * skv[c];
            g_sbias[(b << 8) + pos] = 0.125f * LOG2E * a;
        }
        __syncthreads();
    }
}

// ---------------------------------------------------------------------------
// Kernel C: fp16 m16n8k16 attention (R9 structure); fragment-ordered B,
// register softmax (exp2, scales pre-folded), zero-shuffle P handoff.
// smem: sG 32KB, sVW 32KB, sbias 1KB, sbo 256B
// ---------------------------------------------------------------------------
#define AT_SMEM (32768 + 32768 + 1024 + 256)

__global__ void __launch_bounds__(256, 1) attn_kernel(
    const float* __restrict__ inp,
    const float* __restrict__ bo_g,
    float* __restrict__ out)
{
    extern __shared__ char smem[];
    uint2* sG    = (uint2*)smem;                    // 4096 uint2
    uint2* sVW   = (uint2*)(smem + 32768);          // 4096 uint2
    float* sbias = (float*)(smem + 65536);          // 256
    float* sbo   = (float*)(smem + 66560);          // 64

    int t = threadIdx.x, lane = t & 31, w = t >> 5;
    int lq = lane >> 2, lr = lane & 3;
    int m0 = w * 16;
    int b  = blockIdx.y;
    int n0 = blockIdx.x * 128;

    // ---- A-fragments of X from global, fp16 (k=64 -> 4 ksteps) ----
    uint32_t afr[4][4];
    {
        const float* x0 = inp + ((size_t)(b * NQ + n0 + m0 + lq)) * 64;
        const float* x1 = x0 + 8 * 64;
#pragma unroll
        for (int ks = 0; ks < 4; ++ks) {
            float2 u0 = *(const float2*)&x0[ks * 16 + 2 * lr];
            float2 u1 = *(const float2*)&x1[ks * 16 + 2 * lr];
            float2 u2 = *(const float2*)&x0[ks * 16 + 8 + 2 * lr];
            float2 u3 = *(const float2*)&x1[ks * 16 + 8 + 2 * lr];
            afr[ks][0] = pack_h2(u0.x, u0.y);
            afr[ks][1] = pack_h2(u1.x, u1.y);
            afr[ks][2] = pack_h2(u2.x, u2.y);
            afr[ks][3] = pack_h2(u3.x, u3.y);
        }
    }

    // ---- stage fragment blobs (linear copies) ----
    {
        const uint4* gG = (const uint4*)g_Gh + b * 2048;
        const uint4* gV = (const uint4*)g_VWh + b * 2048;
#pragma unroll
        for (int it = 0; it < 8; ++it) {
            ((uint4*)sG)[it * 256 + t]  = gG[it * 256 + t];
            ((uint4*)sVW)[it * 256 + t] = gV[it * 256 + t];
        }
    }
    if (t < 64) ((float4*)sbias)[t] = ((const float4*)(g_sbias + (b << 8)))[t];
    if (t < 16) ((float4*)sbo)[t]   = ((const float4*)bo_g)[t];
    __syncthreads();

    // ---- GEMM1: S = X @ G^T, 128 mma + 128 LDS.64 per warp ----
    float acc[32][4];
#pragma unroll
    for (int nt = 0; nt < 32; ++nt)
#pragma unroll
        for (int i = 0; i < 4; ++i) acc[nt][i] = 0.0f;

#pragma unroll
    for (int ks = 0; ks < 4; ++ks) {
#pragma unroll
        for (int nt = 0; nt < 32; ++nt) {
            uint2 bb = sG[(nt * 4 + ks) * 32 + lane];
            mma_f16(acc[nt], afr[ks], bb.x, bb.y);
        }
    }

    // ---- softmax in regs (log2 domain): +bias, row max, exp2, row sums ----
    float mx0 = -1e30f, mx1 = -1e30f;
#pragma unroll
    for (int nt = 0; nt < 32; ++nt) {
        int c = nt * 8 + 2 * lr;
        float bi0 = sbias[c], bi1 = sbias[c + 1];
        acc[nt][0] += bi0; acc[nt][1] += bi1;
        acc[nt][2] += bi0; acc[nt][3] += bi1;
        mx0 = fmaxf(mx0, fmaxf(acc[nt][0], acc[nt][1]));
        mx1 = fmaxf(mx1, fmaxf(acc[nt][2], acc[nt][3]));
    }
    mx0 = fmaxf(mx0, __shfl_xor_sync(0xffffffffu, mx0, 1));
    mx0 = fmaxf(mx0, __shfl_xor_sync(0xffffffffu, mx0, 2));
    mx1 = fmaxf(mx1, __shfl_xor_sync(0xffffffffu, mx1, 1));
    mx1 = fmaxf(mx1, __shfl_xor_sync(0xffffffffu, mx1, 2));

    float sum0 = 0.0f, sum1 = 0.0f;
#pragma unroll
    for (int nt = 0; nt < 32; ++nt) {
        float e0 = exp2f(acc[nt][0] - mx0);
        float e1 = exp2f(acc[nt][1] - mx0);
        float e2 = exp2f(acc[nt][2] - mx1);
        float e3 = exp2f(acc[nt][3] - mx1);
        sum0 += e0 + e1;
        sum1 += e2 + e3;
        acc[nt][0] = e0; acc[nt][1] = e1;
        acc[nt][2] = e2; acc[nt][3] = e3;
    }
    sum0 += __shfl_xor_sync(0xffffffffu, sum0, 1);
    sum0 += __shfl_xor_sync(0xffffffffu, sum0, 2);
    sum1 += __shfl_xor_sync(0xffffffffu, sum1, 1);
    sum1 += __shfl_xor_sync(0xffffffffu, sum1, 2);
    float rv0 = 1.0f / sum0;
    float rv1 = 1.0f / sum1;

    // ---- GEMM2: O = P @ VW^T; A-frags = packed own C-frags (no shfl) ----
    float acc2[8][4];
#pragma unroll
    for (int ct = 0; ct < 8; ++ct)
#pragma unroll
        for (int i = 0; i < 4; ++i) acc2[ct][i] = 0.0f;

#pragma unroll
    for (int ks = 0; ks < 16; ++ks) {
        uint32_t pa[4];
        pa[0] = pack_h2(acc[2 * ks][0],     acc[2 * ks][1]);
        pa[1] = pack_h2(acc[2 * ks][2],     acc[2 * ks][3]);
        pa[2] = pack_h2(acc[2 * ks + 1][0], acc[2 * ks + 1][1]);
        pa[3] = pack_h2(acc[2 * ks + 1][2], acc[2 * ks + 1][3]);
#pragma unroll
        for (int ct = 0; ct < 8; ++ct) {
            uint2 bb = sVW[(ct * 16 + ks) * 32 + lane];
            mma_f16(acc2[ct], pa, bb.x, bb.y);
        }
    }

    // ---- epilogue ----
    {
        size_t rg = (size_t)(b * NQ + n0 + m0 + lq) * 64;
#pragma unroll
        for (int ct = 0; ct < 8; ++ct) {
            int c = ct * 8 + 2 * lr;
            float2 o0 = make_float2(acc2[ct][0] * rv0 + sbo[c],
                                    acc2[ct][1] * rv0 + sbo[c + 1]);
            float2 o1 = make_float2(acc2[ct][2] * rv1 + sbo[c],
                                    acc2[ct][3] * rv1 + sbo[c + 1]);
            *(float2*)&out[rg + c] = o0;
            *(float2*)&out[rg + 8 * 64 + c] = o1;
        }
    }
}

// ---------------------------------------------------------------------------
extern "C" void kernel_launch(void* const* d_in, const int* in_sizes, int n_in,
                              void* d_out, int out_size)
{
    const float* inp   = (const float*)d_in[0];
    const float* Wq    = (const float*)d_in[1];
    const float* bq    = (const float*)d_in[2];
    const float* Wkv   = (const float*)d_in[3];
    const float* bkv   = (const float*)d_in[4];
    const float* Wo    = (const float*)d_in[5];
    const float* bo    = (const float*)d_in[6];
    const float* convw = (const float*)d_in[7];
    const float* convb = (const float*)d_in[8];
    const float* gamma = (const float*)d_in[9];
    const float* beta  = (const float*)d_in[10];
    float* out = (float*)d_out;

    const int smemB = 17026 * 4;
    cudaFuncSetAttribute(conv_kernel, cudaFuncAttributeMaxDynamicSharedMemorySize, CV_SMEM);
    cudaFuncSetAttribute(kv_kernel,   cudaFuncAttributeMaxDynamicSharedMemorySize, smemB);
    cudaFuncSetAttribute(attn_kernel, cudaFuncAttributeMaxDynamicSharedMemorySize, AT_SMEM);

    conv_kernel<<<128, 256, CV_SMEM>>>(inp, convw, convb);
    kv_kernel<<<512, 256, smemB>>>(Wq, bq, Wkv, bkv, Wo, gamma, beta);
    attn_kernel<<<dim3(128, 16), 256, AT_SMEM>>>(inp, bo, out);
}

// round 14
// speedup vs baseline: 1.2187x; 1.0018x over previous
#include <cuda_runtime.h>
#include <cuda_fp16.h>
#include <cstdint>

#define BATCH 16
#define NQ    16384
#define CH    64
#define NKV   256
#define EPS   1e-5f
#define LOG2E 1.44269504088896340736f

// Scratch (device globals — no allocation allowed)
__device__ float  g_xconv[BATCH * NKV * CH];  // conv output [b*256+pos][c]
__device__ __half g_Gh[BATCH * 16384];        // G frags (pre-scaled 0.125*log2e)
__device__ __half g_VWh[BATCH * 16384];       // VW frags
__device__ float  g_sbias[BATCH * NKV];       // log2e*0.125*(bq . k_j)

__device__ __forceinline__ uint32_t to_tf32(float f) {
    uint32_t r; asm("cvt.rna.tf32.f32 %0, %1;" : "=r"(r) : "f"(f)); return r;
}
__device__ __forceinline__ uint32_t pack_h2(float lo, float hi) {
    __half2 h = __floats2half2_rn(lo, hi);
    return *(uint32_t*)&h;
}

// tf32: D += A(16x8) @ B(8x8)
__device__ __forceinline__ void mma_tf32(float* d, const uint32_t* a,
                                         uint32_t b0, uint32_t b1) {
    asm volatile(
        "mma.sync.aligned.m16n8k8.row.col.f32.tf32.tf32.f32 "
        "{%0,%1,%2,%3}, {%4,%5,%6,%7}, {%8,%9}, {%0,%1,%2,%3};"
        : "+f"(d[0]), "+f"(d[1]), "+f"(d[2]), "+f"(d[3])
        : "r"(a[0]), "r"(a[1]), "r"(a[2]), "r"(a[3]), "r"(b0), "r"(b1));
}
// fp16: D += A(16x16) @ B(16x8), fp32 accum
__device__ __forceinline__ void mma_f16(float* d, const uint32_t* a,
                                        uint32_t b0, uint32_t b1) {
    asm volatile(
        "mma.sync.aligned.m16n8k16.row.col.f32.f16.f16.f32 "
        "{%0,%1,%2,%3}, {%4,%5,%6,%7}, {%8,%9}, {%0,%1,%2,%3};"
        : "+f"(d[0]), "+f"(d[1]), "+f"(d[2]), "+f"(d[3])
        : "r"(a[0]), "r"(a[1]), "r"(a[2]), "r"(a[3]), "r"(b0), "r"(b1));
}

// ---------------------------------------------------------------------------
// Kernel A: strided conv as GEMM via tf32 mma.sync.
// R9 structure (register prefetch, 2 syncs/iter) but 512 threads / 16 warps:
// warp tile 16 rows x 8 cols -> 4 warps per SMSP (latency hiding via
// parallelism, which R11/R12 pipelining failed to deliver).
// sA [r][k] ld 68, sW [k][c] ld 72 — both conflict-free for frag loads.
// ---------------------------------------------------------------------------
__global__ void __launch_bounds__(512, 1) conv_kernel(
    const float* __restrict__ inp,
    const float* __restrict__ convw,
    const float* __restrict__ convb)
{
    __shared__ float sA[32 * 68];
    __shared__ float sW[64 * 72];

    int t = threadIdx.x, lane = t & 31, w = t >> 5;
    int lq = lane >> 2, lr = lane & 3;
    int rg16 = (w >> 3) * 16;      // 2 rowgroups
    int cb   = (w & 7) * 8;        // 8 colgroups

    // A-load metadata: 1 float4 per thread (32 rows x 16 f4)
    int r  = t >> 4;
    int kk = (t & 15) * 4;
    int rgl = blockIdx.x * 32 + r;
    int bb_ = rgl >> 8;
    int patch = rgl & 255;
    int pi = patch >> 4, pj = patch & 15;
    int rowbase = (bb_ << 14) + (pi << 10) + (pj << 3);

    // W-load metadata: 2 float4 per thread (64 rows x 16 f4)
    int kin[2], c4[2];
#pragma unroll
    for (int it = 0; it < 2; ++it) {
        int f4i = it * 512 + t;
        kin[it] = f4i >> 4;
        c4[it]  = (f4i & 15) * 4;
    }

    float acc[4] = {};
    float4 pa, pw[2];

    // prefetch iter 0
    pa = *(const float4*)&inp[(rowbase << 6) + kk];
#pragma unroll
    for (int it = 0; it < 2; ++it)
        pw[it] = *(const float4*)&convw[kin[it] * 64 + c4[it]];

    for (int kc = 0; kc < 64; ++kc) {
        // commit prefetched tiles (tf32 RNA converted)
        {
            uint4 u = make_uint4(to_tf32(pa.x), to_tf32(pa.y), to_tf32(pa.z), to_tf32(pa.w));
            *(uint4*)&sA[r * 68 + kk] = u;
        }
#pragma unroll
        for (int it = 0; it < 2; ++it) {
            float4 v = pw[it];
            uint4 u = make_uint4(to_tf32(v.x), to_tf32(v.y), to_tf32(v.z), to_tf32(v.w));
            *(uint4*)&sW[kin[it] * 72 + c4[it]] = u;
        }
        __syncthreads();

        // prefetch next iter into registers (latency overlaps compute)
        if (kc + 1 < 64) {
            int kn = kc + 1, di = kn >> 3, dj = kn & 7;
            pa = *(const float4*)&inp[((rowbase + di * 128 + dj) << 6) + kk];
#pragma unroll
            for (int it = 0; it < 2; ++it)
                pw[it] = *(const float4*)&convw[(kn << 12) + kin[it] * 64 + c4[it]];
        }

        // compute: 8 k-steps x 1 nb per warp
#pragma unroll
        for (int k = 0; k < 8; ++k) {
            uint32_t a[4];
            a[0] = __float_as_uint(sA[(rg16 + lq) * 68 + k * 8 + lr]);
            a[1] = __float_as_uint(sA[(rg16 + 8 + lq) * 68 + k * 8 + lr]);
            a[2] = __float_as_uint(sA[(rg16 + lq) * 68 + k * 8 + lr + 4]);
            a[3] = __float_as_uint(sA[(rg16 + 8 + lq) * 68 + k * 8 + lr + 4]);
            uint32_t b0 = __float_as_uint(sW[(k * 8 + lr) * 72 + cb + lq]);
            uint32_t b1 = __float_as_uint(sW[(k * 8 + lr + 4) * 72 + cb + lq]);
            mma_tf32(acc, a, b0, b1);
        }
        __syncthreads();
    }

    // epilogue
    int row0 = blockIdx.x * 32 + rg16 + lq;
    {
        int c = cb + 2 * lr;
        float cb0 = convb[c], cb1 = convb[c + 1];
        *(float2*)&g_xconv[row0 * 64 + c] =
            make_float2(acc[0] + cb0, acc[1] + cb1);
        *(float2*)&g_xconv[(row0 + 8) * 64 + c] =
            make_float2(acc[2] + cb0, acc[3] + cb1);
    }
}

// ---------------------------------------------------------------------------
// Kernel B: per kv position — LN, kv proj; emits FRAGMENT-ORDERED fp16 G/VW.
// G pre-scaled by 0.125*log2(e); sbias by 0.125*log2(e)  (softmax uses exp2).
// ---------------------------------------------------------------------------
__global__ void __launch_bounds__(256, 1) kv_kernel(
    const float* __restrict__ Wq,  const float* __restrict__ bq,
    const float* __restrict__ Wkv, const float* __restrict__ bkv,
    const float* __restrict__ Wo,
    const float* __restrict__ gamma, const float* __restrict__ beta)
{
    extern __shared__ float sm[];
    float* sWkv = sm;            // 8192
    float* sWo  = sm + 8192;     // 4096
    float* sWqT = sm + 12288;    // 64*65
    float* sx   = sm + 16448;
    float* sxn  = sm + 16512;
    float* skv  = sm + 16576;
    float* sgam = sm + 16704;
    float* sbet = sm + 16768;
    float* sbq  = sm + 16832;
    float* sbkv = sm + 16896;
    float* sstat= sm + 17024;

    int t = threadIdx.x;

#pragma unroll
    for (int it = 0; it < 8; ++it)
        ((float4*)sWkv)[it * 256 + t] = ((const float4*)Wkv)[it * 256 + t];
#pragma unroll
    for (int it = 0; it < 4; ++it)
        ((float4*)sWo)[it * 256 + t] = ((const float4*)Wo)[it * 256 + t];
#pragma unroll
    for (int it = 0; it < 4; ++it) {
        int f4i = it * 256 + t;
        int d = f4i >> 4, cc = (f4i & 15) * 4;
        float4 v = ((const float4*)Wq)[f4i];
        sWqT[(cc + 0) * 65 + d] = v.x;
        sWqT[(cc + 1) * 65 + d] = v.y;
        sWqT[(cc + 2) * 65 + d] = v.z;
        sWqT[(cc + 3) * 65 + d] = v.w;
    }
    if (t < 64)  { sgam[t] = gamma[t]; sbet[t] = beta[t]; sbq[t] = bq[t]; }
    if (t < 128) { sbkv[t] = bkv[t]; }
    __syncthreads();

    for (int p = 0; p < 8; ++p) {
        int j = blockIdx.x * 8 + p;
        if (t < 64) sx[t] = g_xconv[j * 64 + t];
        __syncthreads();

        if (t < 32) {
            float a = sx[t], b2 = sx[t + 32];
            float s = a + b2;
            float q = a * a + b2 * b2;
#pragma unroll
            for (int off = 16; off > 0; off >>= 1) {
                s += __shfl_xor_sync(0xffffffffu, s, off);
                q += __shfl_xor_sync(0xffffffffu, q, off);
            }
            if (t == 0) {
                float mean = s * (1.0f / 64.0f);
                sstat[0] = mean;
                sstat[1] = rsqrtf(q * (1.0f / 64.0f) - mean * mean + EPS);
            }
        }
        __syncthreads();
        if (t < 64)
            sxn[t] = (sx[t] - sstat[0]) * sstat[1] * sgam[t] + sbet[t];
        __syncthreads();

        if (t < 128) {
            float a = sbkv[t];
#pragma unroll 16
            for (int c = 0; c < 64; ++c)
                a += sxn[c] * sWkv[c * 128 + t];
            skv[t] = a;
        }
        __syncthreads();

        int b = j >> 8, pos = j & 255;
        if (t < 64) {
            float a = 0.0f;
#pragma unroll 16
            for (int c = 0; c < 64; ++c)
                a += sWqT[c * 65 + t] * skv[c];
            int nt = pos >> 3, lqj = pos & 7;
            int d = t, ks = d >> 4, dd = d & 15;
            int wrd = dd >> 3, lr = (dd >> 1) & 3, h = dd & 1;
            int idx = ((((b * 32 + nt) * 4 + ks) * 32 + lqj * 4 + lr) * 2 + wrd) * 2 + h;
            g_Gh[idx] = __float2half_rn(0.125f * LOG2E * a);
        } else if (t < 128) {
            int cc = t - 64;
            float a = 0.0f;
#pragma unroll 16
            for (int d = 0; d < 64; ++d)
                a += skv[64 + d] * sWo[d * 64 + cc];
            int ct = cc >> 3, lqc = cc & 7;
            int ks = pos >> 4, jj = pos & 15;
            int wrd = jj >> 3, lr = (jj >> 1) & 3, h = jj & 1;
            int idx = ((((b * 8 + ct) * 16 + ks) * 32 + lqc * 4 + lr) * 2 + wrd) * 2 + h;
            g_VWh[idx] = __float2half_rn(a);
        } else if (t == 128) {
            float a = 0.0f;
            for (int c = 0; c < 64; ++c)
                a += sbq[c] * skv[c];
            g_sbias[(b << 8) + pos] = 0.125f * LOG2E * a;
        }
        __syncthreads();
    }
}

// ---------------------------------------------------------------------------
// Kernel C: fp16 m16n8k16 attention (R9 structure); fragment-ordered B,
// register softmax (exp2, scales pre-folded), zero-shuffle P handoff.
// smem: sG 32KB, sVW 32KB, sbias 1KB, sbo 256B
// ---------------------------------------------------------------------------
#define AT_SMEM (32768 + 32768 + 1024 + 256)

__global__ void __launch_bounds__(256, 1) attn_kernel(
    const float* __restrict__ inp,
    const float* __restrict__ bo_g,
    float* __restrict__ out)
{
    extern __shared__ char smem[];
    uint2* sG    = (uint2*)smem;                    // 4096 uint2
    uint2* sVW   = (uint2*)(smem + 32768);          // 4096 uint2
    float* sbias = (float*)(smem + 65536);          // 256
    float* sbo   = (float*)(smem + 66560);          // 64

    int t = threadIdx.x, lane = t & 31, w = t >> 5;
    int lq = lane >> 2, lr = lane & 3;
    int m0 = w * 16;
    int b  = blockIdx.y;
    int n0 = blockIdx.x * 128;

    // ---- A-fragments of X from global, fp16 (k=64 -> 4 ksteps) ----
    uint32_t afr[4][4];
    {
        const float* x0 = inp + ((size_t)(b * NQ + n0 + m0 + lq)) * 64;
        const float* x1 = x0 + 8 * 64;
#pragma unroll
        for (int ks = 0; ks < 4; ++ks) {
            float2 u0 = *(const float2*)&x0[ks * 16 + 2 * lr];
            float2 u1 = *(const float2*)&x1[ks * 16 + 2 * lr];
            float2 u2 = *(const float2*)&x0[ks * 16 + 8 + 2 * lr];
            float2 u3 = *(const float2*)&x1[ks * 16 + 8 + 2 * lr];
            afr[ks][0] = pack_h2(u0.x, u0.y);
            afr[ks][1] = pack_h2(u1.x, u1.y);
            afr[ks][2] = pack_h2(u2.x, u2.y);
            afr[ks][3] = pack_h2(u3.x, u3.y);
        }
    }

    // ---- stage fragment blobs (linear copies) ----
    {
        const uint4* gG = (const uint4*)g_Gh + b * 2048;
        const uint4* gV = (const uint4*)g_VWh + b * 2048;
#pragma unroll
        for (int it = 0; it < 8; ++it) {
            ((uint4*)sG)[it * 256 + t]  = gG[it * 256 + t];
            ((uint4*)sVW)[it * 256 + t] = gV[it * 256 + t];
        }
    }
    if (t < 64) ((float4*)sbias)[t] = ((const float4*)(g_sbias + (b << 8)))[t];
    if (t < 16) ((float4*)sbo)[t]   = ((const float4*)bo_g)[t];
    __syncthreads();

    // ---- GEMM1: S = X @ G^T, 128 mma + 128 LDS.64 per warp ----
    float acc[32][4];
#pragma unroll
    for (int nt = 0; nt < 32; ++nt)
#pragma unroll
        for (int i = 0; i < 4; ++i) acc[nt][i] = 0.0f;

#pragma unroll
    for (int ks = 0; ks < 4; ++ks) {
#pragma unroll
        for (int nt = 0; nt < 32; ++nt) {
            uint2 bb = sG[(nt * 4 + ks) * 32 + lane];
            mma_f16(acc[nt], afr[ks], bb.x, bb.y);
        }
    }

    // ---- softmax in regs (log2 domain): +bias, row max, exp2, row sums ----
    float mx0 = -1e30f, mx1 = -1e30f;
#pragma unroll
    for (int nt = 0; nt < 32; ++nt) {
        int c = nt * 8 + 2 * lr;
        float bi0 = sbias[c], bi1 = sbias[c + 1];
        acc[nt][0] += bi0; acc[nt][1] += bi1;
        acc[nt][2] += bi0; acc[nt][3] += bi1;
        mx0 = fmaxf(mx0, fmaxf(acc[nt][0], acc[nt][1]));
        mx1 = fmaxf(mx1, fmaxf(acc[nt][2], acc[nt][3]));
    }
    mx0 = fmaxf(mx0, __shfl_xor_sync(0xffffffffu, mx0, 1));
    mx0 = fmaxf(mx0, __shfl_xor_sync(0xffffffffu, mx0, 2));
    mx1 = fmaxf(mx1, __shfl_xor_sync(0xffffffffu, mx1, 1));
    mx1 = fmaxf(mx1, __shfl_xor_sync(0xffffffffu, mx1, 2));

    float sum0 = 0.0f, sum1 = 0.0f;
#pragma unroll
    for (int nt = 0; nt < 32; ++nt) {
        float e0 = exp2f(acc[nt][0] - mx0);
        float e1 = exp2f(acc[nt][1] - mx0);
        float e2 = exp2f(acc[nt][2] - mx1);
        float e3 = exp2f(acc[nt][3] - mx1);
        sum0 += e0 + e1;
        sum1 += e2 + e3;
        acc[nt][0] = e0; acc[nt][1] = e1;
        acc[nt][2] = e2; acc[nt][3] = e3;
    }
    sum0 += __shfl_xor_sync(0xffffffffu, sum0, 1);
    sum0 += __shfl_xor_sync(0xffffffffu, sum0, 2);
    sum1 += __shfl_xor_sync(0xffffffffu, sum1, 1);
    sum1 += __shfl_xor_sync(0xffffffffu, sum1, 2);
    float rv0 = 1.0f / sum0;
    float rv1 = 1.0f / sum1;

    // ---- GEMM2: O = P @ VW^T; A-frags = packed own C-frags (no shfl) ----
    float acc2[8][4];
#pragma unroll
    for (int ct = 0; ct < 8; ++ct)
#pragma unroll
        for (int i = 0; i < 4; ++i) acc2[ct][i] = 0.0f;

#pragma unroll
    for (int ks = 0; ks < 16; ++ks) {
        uint32_t pa[4];
        pa[0] = pack_h2(acc[2 * ks][0],     acc[2 * ks][1]);
        pa[1] = pack_h2(acc[2 * ks][2],     acc[2 * ks][3]);
        pa[2] = pack_h2(acc[2 * ks + 1][0], acc[2 * ks + 1][1]);
        pa[3] = pack_h2(acc[2 * ks + 1][2], acc[2 * ks + 1][3]);
#pragma unroll
        for (int ct = 0; ct < 8; ++ct) {
            uint2 bb = sVW[(ct * 16 + ks) * 32 + lane];
            mma_f16(acc2[ct], pa, bb.x, bb.y);
        }
    }

    // ---- epilogue ----
    {
        size_t rg = (size_t)(b * NQ + n0 + m0 + lq) * 64;
#pragma unroll
        for (int ct = 0; ct < 8; ++ct) {
            int c = ct * 8 + 2 * lr;
            float2 o0 = make_float2(acc2[ct][0] * rv0 + sbo[c],
                                    acc2[ct][1] * rv0 + sbo[c + 1]);
            float2 o1 = make_float2(acc2[ct][2] * rv1 + sbo[c],
                                    acc2[ct][3] * rv1 + sbo[c + 1]);
            *(float2*)&out[rg + c] = o0;
            *(float2*)&out[rg + 8 * 64 + c] = o1;
        }
    }
}

// ---------------------------------------------------------------------------
extern "C" void kernel_launch(void* const* d_in, const int* in_sizes, int n_in,
                              void* d_out, int out_size)
{
    const float* inp   = (const float*)d_in[0];
    const float* Wq    = (const float*)d_in[1];
    const float* bq    = (const float*)d_in[2];
    const float* Wkv   = (const float*)d_in[3];
    const float* bkv   = (const float*)d_in[4];
    const float* Wo    = (const float*)d_in[5];
    const float* bo    = (const float*)d_in[6];
    const float* convw = (const float*)d_in[7];
    const float* convb = (const float*)d_in[8];
    const float* gamma = (const float*)d_in[9];
    const float* beta  = (const float*)d_in[10];
    float* out = (float*)d_out;

    const int smemB = 17026 * 4;
    cudaFuncSetAttribute(kv_kernel,   cudaFuncAttributeMaxDynamicSharedMemorySize, smemB);
    cudaFuncSetAttribute(attn_kernel, cudaFuncAttributeMaxDynamicSharedMemorySize, AT_SMEM);

    conv_kernel<<<128, 512>>>(inp, convw, convb);
    kv_kernel<<<512, 256, smemB>>>(Wq, bq, Wkv, bkv, Wo, gamma, beta);
    attn_kernel<<<dim3(128, 16), 256, AT_SMEM>>>(inp, bo, out);
}